// round 15
// baseline (speedup 1.0000x reference)
#include <cuda_runtime.h>
#include <cuda_bf16.h>
#include <cstdint>

// Problem dims (fixed): B=4, S=4096, D=2048, Db=512
#define T_ROWS 16384
#define DIM    2048
#define DBOT   512
#define LN_EPS 1e-5f

// bf16 GEMM tiling (BYTE units in the mainloop; bf16 = 2 B/elt)
#define BM 64
#define BN 64
#define KTB 64                         // K bytes per tile (= 32 bf16 elements)
#define BKB 80                         // padded row stride bytes (16B-aligned cp.async, conflict-free)
#define STAGES 4
#define STAGE_BYTES ((BM + BN) * BKB)  // 10240
#define DYN_BYTES (STAGES * STAGE_BYTES)  // 40960
#define THREADS 128

// ---------------------------------------------------------------------------
// Device scratch (allocation forbidden -> __device__ globals)
// ---------------------------------------------------------------------------
__device__ __nv_bfloat16 g_hn[(size_t)T_ROWS * DIM];   // 64 MB normalized hidden (bf16)
__device__ __nv_bfloat16 g_z[(size_t)T_ROWS * DBOT];   // 16 MB bottleneck activations
__device__ __nv_bfloat16 g_WdT[(size_t)DBOT * DIM];    // W_down^T bf16  [n][k]
__device__ __nv_bfloat16 g_WuT[(size_t)DIM * DBOT];    // W_up^T   bf16  [n][k]

// ---------------------------------------------------------------------------
// PTX helpers
// ---------------------------------------------------------------------------
__device__ __forceinline__ unsigned smem_u32(const void* p) {
    return (unsigned)__cvta_generic_to_shared(p);
}
__device__ __forceinline__ void cpa16(unsigned dst, const void* src) {
    asm volatile("cp.async.cg.shared.global [%0], [%1], 16;\n" :: "r"(dst), "l"(src));
}
__device__ __forceinline__ void cpa_commit() {
    asm volatile("cp.async.commit_group;\n");
}
template <int N>
__device__ __forceinline__ void cpa_wait() {
    asm volatile("cp.async.wait_group %0;\n" :: "n"(N));
}
__device__ __forceinline__ void ldsm_x4(unsigned& r0, unsigned& r1, unsigned& r2, unsigned& r3,
                                        unsigned addr) {
    asm volatile("ldmatrix.sync.aligned.m8n8.x4.shared.b16 {%0,%1,%2,%3}, [%4];\n"
                 : "=r"(r0), "=r"(r1), "=r"(r2), "=r"(r3) : "r"(addr));
}
__device__ __forceinline__ void mma16816(float c[4], const unsigned a[4], const unsigned b[2]) {
    asm volatile(
        "mma.sync.aligned.m16n8k16.row.col.f32.bf16.bf16.f32 "
        "{%0,%1,%2,%3}, {%4,%5,%6,%7}, {%8,%9}, {%0,%1,%2,%3};\n"
        : "+f"(c[0]), "+f"(c[1]), "+f"(c[2]), "+f"(c[3])
        : "r"(a[0]), "r"(a[1]), "r"(a[2]), "r"(a[3]), "r"(b[0]), "r"(b[1]));
}
__device__ __forceinline__ float silu(float v) {
    return v * (1.f / (1.f + __expf(-v)));
}
__device__ __forceinline__ uint2 pack4(float a, float b, float c, float d) {
    __nv_bfloat162 p0 = __floats2bfloat162_rn(a, b);
    __nv_bfloat162 p1 = __floats2bfloat162_rn(c, d);
    uint2 u;
    u.x = *reinterpret_cast<unsigned*>(&p0);
    u.y = *reinterpret_cast<unsigned*>(&p1);
    return u;
}

// ---------------------------------------------------------------------------
// Fused LayerNorm -> bf16 h_norm (one block per row, read+write once)
// ---------------------------------------------------------------------------
__global__ __launch_bounds__(256) void ln_norm_kernel(
    const float* __restrict__ hidden,
    const float* __restrict__ gamma,
    const float* __restrict__ beta)
{
    const int row = blockIdx.x;
    const int t = threadIdx.x;
    const int warp = t >> 5, lane = t & 31;

    const float4* hp = reinterpret_cast<const float4*>(hidden + (size_t)row * DIM);
    float4 v0 = hp[t], v1 = hp[t + 256];

    float s  = v0.x + v0.y + v0.z + v0.w + v1.x + v1.y + v1.z + v1.w;
    float ss = v0.x * v0.x + v0.y * v0.y + v0.z * v0.z + v0.w * v0.w
             + v1.x * v1.x + v1.y * v1.y + v1.z * v1.z + v1.w * v1.w;
#pragma unroll
    for (int o = 16; o > 0; o >>= 1) {
        s  += __shfl_xor_sync(0xffffffffu, s, o);
        ss += __shfl_xor_sync(0xffffffffu, ss, o);
    }
    __shared__ float rs[8], rss[8], stats[2];
    if (lane == 0) { rs[warp] = s; rss[warp] = ss; }
    __syncthreads();
    if (warp == 0) {
        float s2  = (lane < 8) ? rs[lane]  : 0.f;
        float ss2 = (lane < 8) ? rss[lane] : 0.f;
#pragma unroll
        for (int o = 4; o > 0; o >>= 1) {
            s2  += __shfl_xor_sync(0xffffffffu, s2, o);
            ss2 += __shfl_xor_sync(0xffffffffu, ss2, o);
        }
        if (lane == 0) {
            float mu  = s2 * (1.f / DIM);
            float var = ss2 * (1.f / DIM) - mu * mu;
            stats[0] = mu;
            stats[1] = rsqrtf(var + LN_EPS);
        }
    }
    __syncthreads();
    const float mu = stats[0], rstd = stats[1];

    const float4* gp = reinterpret_cast<const float4*>(gamma);
    const float4* bp = reinterpret_cast<const float4*>(beta);
    float4 g0 = gp[t], g1 = gp[t + 256];
    float4 b0 = bp[t], b1 = bp[t + 256];

    uint2* dst = reinterpret_cast<uint2*>(g_hn + (size_t)row * DIM);
    dst[t] = pack4((v0.x - mu) * rstd * g0.x + b0.x,
                   (v0.y - mu) * rstd * g0.y + b0.y,
                   (v0.z - mu) * rstd * g0.z + b0.z,
                   (v0.w - mu) * rstd * g0.w + b0.w);
    dst[t + 256] = pack4((v1.x - mu) * rstd * g1.x + b1.x,
                         (v1.y - mu) * rstd * g1.y + b1.y,
                         (v1.z - mu) * rstd * g1.z + b1.z,
                         (v1.w - mu) * rstd * g1.w + b1.w);
}

// ---------------------------------------------------------------------------
// fp32 [R][C] -> bf16 transposed [C][R]
// ---------------------------------------------------------------------------
__global__ void transpose_bf16_kernel(const float* __restrict__ src, int R, int C,
                                      __nv_bfloat16* __restrict__ dst)
{
    __shared__ float tile[32][33];
    int x  = blockIdx.x * 32 + threadIdx.x;
    int y0 = blockIdx.y * 32;
#pragma unroll
    for (int j = 0; j < 32; j += 8)
        tile[threadIdx.y + j][threadIdx.x] = src[(size_t)(y0 + threadIdx.y + j) * C + x];
    __syncthreads();
    int xr  = blockIdx.y * 32 + threadIdx.x;
    int yc0 = blockIdx.x * 32;
#pragma unroll
    for (int j = 0; j < 32; j += 8)
        dst[(size_t)(yc0 + threadIdx.y + j) * R + xr] =
            __float2bfloat16_rn(tile[threadIdx.x][threadIdx.y + j]);
}

// ---------------------------------------------------------------------------
// bf16 GEMM mainloop (BYTE addressing, identical layout to the verified R14
// fp8 loop: 64B K-tiles in 80B padded rows, two 32B k-steps per tile).
// 64x64 CTA tile, 4 warps (warp tile 32x32), 4-stage cp.async pipeline
// unrolled by 4, one 128-thread __syncthreads per K-tile.
// Fragment double-buffering: LDSM for k-step k+1 issues before the MMAs of
// k-step k -> LDSM latency covered by in-flight MMAs (this is the fix for
// bf16's issue=18.9% latency stall; bf16 has no fp8 conversion tax).
// Cross-tile prefetch uses wait_group<1>; slot is not refilled until 2 syncs
// later -> no WAR hazard.
// ---------------------------------------------------------------------------
__device__ __forceinline__ void gemm_mainloop(
    const unsigned char* __restrict__ Ag, int ldaB,
    const unsigned char* __restrict__ Bg, int ldbB,
    int KBytes, int rowBase, int n0,
    unsigned sbase,
    float c[2][4][4])
{
    const int tid  = threadIdx.x;
    const int warp = tid >> 5, lane = tid & 31;
    const int wm = warp >> 1, wn = warp & 1;     // 2x2 warp grid, 32x32 tiles

    const int aRow     = ((lane >> 3) & 1) * 8 + (lane & 7);
    const int aColOffB = (lane >> 4) * 16;
    const int bRow     = (lane >> 4) * 8 + (lane & 7);
    const int bColOffB = ((lane >> 3) & 1) * 16;

    // warp-invariant fragment base addresses (slot 0, k-offset 0)
    unsigned aBase[2], bBase[2];
#pragma unroll
    for (int mi = 0; mi < 2; ++mi)
        aBase[mi] = sbase + (unsigned)((wm * 32 + mi * 16 + aRow) * BKB + aColOffB);
#pragma unroll
    for (int p = 0; p < 2; ++p)
        bBase[p] = sbase + (unsigned)(BM * BKB + (wn * 32 + p * 16 + bRow) * BKB + bColOffB);

    // per-thread load state: 2 A rows + 2 B rows, 16B each
    const int r0i = tid >> 2;            // 0..31
    const int ci  = (tid & 3) * 16;      // 0..48
    const unsigned dA0 = sbase + (unsigned)(r0i * BKB + ci);
    const unsigned dA1 = sbase + (unsigned)((r0i + 32) * BKB + ci);
    const unsigned dB0 = sbase + (unsigned)(BM * BKB + r0i * BKB + ci);
    const unsigned dB1 = sbase + (unsigned)(BM * BKB + (r0i + 32) * BKB + ci);
    const unsigned char* pA0 = Ag + (size_t)(rowBase + r0i) * ldaB + ci;
    const unsigned char* pA1 = pA0 + (size_t)32 * ldaB;
    const unsigned char* pB0 = Bg + (size_t)(n0 + r0i) * ldbB + ci;
    const unsigned char* pB1 = pB0 + (size_t)32 * ldbB;

    const int niter = KBytes / KTB;   // 64 (gemm1) / 16 (gemm2): multiples of 4

    // prologue: tiles 0..2 -> slots 0..2
#pragma unroll
    for (int s = 0; s < 3; ++s) {
        const unsigned off = (unsigned)(s * STAGE_BYTES);
        cpa16(dA0 + off, pA0); cpa16(dA1 + off, pA1);
        cpa16(dB0 + off, pB0); cpa16(dB1 + off, pB1);
        cpa_commit();
        pA0 += KTB; pA1 += KTB; pB0 += KTB; pB1 += KTB;
    }

    // fragment double buffers
    unsigned a0[2][4], a1[2][4], b0[4][2], b1[4][2];

    // wait tile 0, preload its k-step-0 fragments
    cpa_wait<2>();
    __syncthreads();
#pragma unroll
    for (int mi = 0; mi < 2; ++mi)
        ldsm_x4(a0[mi][0], a0[mi][1], a0[mi][2], a0[mi][3], aBase[mi]);
#pragma unroll
    for (int p = 0; p < 2; ++p)
        ldsm_x4(b0[2 * p][0], b0[2 * p][1], b0[2 * p + 1][0], b0[2 * p + 1][1], bBase[p]);

    for (int it4 = 0; it4 < niter; it4 += 4) {
#pragma unroll
        for (int u = 0; u < 4; ++u) {       // slot = u (compile-time)
            const int it = it4 + u;
            cpa_wait<1>();                  // tiles <= it+1 resident
            __syncthreads();                // WAR: slot (u+3)&3 free

            if (it + 3 < niter) {
                const unsigned off = (unsigned)(((u + 3) & 3) * STAGE_BYTES);
                cpa16(dA0 + off, pA0); cpa16(dA1 + off, pA1);
                cpa16(dB0 + off, pB0); cpa16(dB1 + off, pB1);
                pA0 += KTB; pA1 += KTB; pB0 += KTB; pB1 += KTB;
            }
            cpa_commit();

            const unsigned sCur = (unsigned)(u * STAGE_BYTES);
            const unsigned sNxt = (unsigned)(((u + 1) & 3) * STAGE_BYTES);

            // ---- k-step 0: prefetch this tile's k1 frags, compute k0
#pragma unroll
            for (int mi = 0; mi < 2; ++mi)
                ldsm_x4(a1[mi][0], a1[mi][1], a1[mi][2], a1[mi][3],
                        aBase[mi] + sCur + 32u);
#pragma unroll
            for (int p = 0; p < 2; ++p)
                ldsm_x4(b1[2 * p][0], b1[2 * p][1], b1[2 * p + 1][0], b1[2 * p + 1][1],
                        bBase[p] + sCur + 32u);
#pragma unroll
            for (int mi = 0; mi < 2; ++mi)
#pragma unroll
                for (int ni = 0; ni < 4; ++ni)
                    mma16816(c[mi][ni], a0[mi], b0[ni]);

            // ---- k-step 1: prefetch next tile's k0 frags, compute k1
            if (it + 1 < niter) {
#pragma unroll
                for (int mi = 0; mi < 2; ++mi)
                    ldsm_x4(a0[mi][0], a0[mi][1], a0[mi][2], a0[mi][3],
                            aBase[mi] + sNxt);
#pragma unroll
                for (int p = 0; p < 2; ++p)
                    ldsm_x4(b0[2 * p][0], b0[2 * p][1], b0[2 * p + 1][0], b0[2 * p + 1][1],
                            bBase[p] + sNxt);
            }
#pragma unroll
            for (int mi = 0; mi < 2; ++mi)
#pragma unroll
                for (int ni = 0; ni < 4; ++ni)
                    mma16816(c[mi][ni], a1[mi], b1[ni]);
        }
    }
}

// ---------------------------------------------------------------------------
// GEMM1: z = SiLU( h_norm @ W_down + b_down )   (bf16 out to g_z)
// ---------------------------------------------------------------------------
__global__ __launch_bounds__(THREADS, 5) void gemm1_kernel(const float* __restrict__ bd)
{
    extern __shared__ __align__(16) unsigned char smem[];

    const int tid  = threadIdx.x;
    const int warp = tid >> 5, lane = tid & 31;
    const int wm = warp >> 1, wn = warp & 1;
    const int group = lane >> 2, tg = lane & 3;
    const int rowBase = blockIdx.y * BM;
    const int n0      = blockIdx.x * BN;

    float c[2][4][4];
#pragma unroll
    for (int i = 0; i < 2; i++)
#pragma unroll
        for (int j = 0; j < 4; j++)
#pragma unroll
            for (int k = 0; k < 4; k++) c[i][j][k] = 0.f;

    gemm_mainloop((const unsigned char*)g_hn, DIM * 2,
                  (const unsigned char*)g_WdT, DIM * 2,
                  DIM * 2, rowBase, n0, smem_u32(smem), c);

#pragma unroll
    for (int mi = 0; mi < 2; ++mi) {
        int r0 = rowBase + wm * 32 + mi * 16 + group;
#pragma unroll
        for (int ni = 0; ni < 4; ++ni) {
            int cc = n0 + wn * 32 + ni * 8 + tg * 2;
            float bd0 = bd[cc], bd1 = bd[cc + 1];
            *reinterpret_cast<__nv_bfloat162*>(&g_z[(size_t)r0 * DBOT + cc]) =
                __floats2bfloat162_rn(silu(c[mi][ni][0] + bd0), silu(c[mi][ni][1] + bd1));
            *reinterpret_cast<__nv_bfloat162*>(&g_z[(size_t)(r0 + 8) * DBOT + cc]) =
                __floats2bfloat162_rn(silu(c[mi][ni][2] + bd0), silu(c[mi][ni][3] + bd1));
        }
    }
}

// ---------------------------------------------------------------------------
// GEMM2: out = hidden + alpha * ( z @ W_up + b_up - hidden )
// ---------------------------------------------------------------------------
__global__ __launch_bounds__(THREADS, 5) void gemm2_kernel(
    const float* __restrict__ hidden,
    const float* __restrict__ bu,
    const float* __restrict__ alpha_p,
    float* __restrict__ out)
{
    extern __shared__ __align__(16) unsigned char smem[];

    const int tid  = threadIdx.x;
    const int warp = tid >> 5, lane = tid & 31;
    const int wm = warp >> 1, wn = warp & 1;
    const int group = lane >> 2, tg = lane & 3;
    const int rowBase = blockIdx.y * BM;
    const int n0      = blockIdx.x * BN;

    float c[2][4][4];
#pragma unroll
    for (int i = 0; i < 2; i++)
#pragma unroll
        for (int j = 0; j < 4; j++)
#pragma unroll
            for (int k = 0; k < 4; k++) c[i][j][k] = 0.f;

    gemm_mainloop((const unsigned char*)g_z, DBOT * 2,
                  (const unsigned char*)g_WuT, DBOT * 2,
                  DBOT * 2, rowBase, n0, smem_u32(smem), c);

    const float al = alpha_p[0];
#pragma unroll
    for (int mi = 0; mi < 2; ++mi) {
        int r0 = rowBase + wm * 32 + mi * 16 + group;
        int r1 = r0 + 8;
#pragma unroll
        for (int ni = 0; ni < 4; ++ni) {
            int cc = n0 + wn * 32 + ni * 8 + tg * 2;
            float bu0 = bu[cc], bu1 = bu[cc + 1];

            float2 h0 = *reinterpret_cast<const float2*>(hidden + (size_t)r0 * DIM + cc);
            float2 h1 = *reinterpret_cast<const float2*>(hidden + (size_t)r1 * DIM + cc);

            float2 o0, o1;
            o0.x = h0.x + al * (c[mi][ni][0] + bu0 - h0.x);
            o0.y = h0.y + al * (c[mi][ni][1] + bu1 - h0.y);
            o1.x = h1.x + al * (c[mi][ni][2] + bu0 - h1.x);
            o1.y = h1.y + al * (c[mi][ni][3] + bu1 - h1.y);

            *reinterpret_cast<float2*>(out + (size_t)r0 * DIM + cc) = o0;
            *reinterpret_cast<float2*>(out + (size_t)r1 * DIM + cc) = o1;
        }
    }
}

// ---------------------------------------------------------------------------
// Launch
// ---------------------------------------------------------------------------
extern "C" void kernel_launch(void* const* d_in, const int* in_sizes, int n_in,
                              void* d_out, int out_size) {
    const float* hidden = (const float*)d_in[0];
    const float* gamma  = (const float*)d_in[1];
    const float* beta   = (const float*)d_in[2];
    const float* Wd     = (const float*)d_in[3];
    const float* bd     = (const float*)d_in[4];
    const float* Wu     = (const float*)d_in[5];
    const float* bu     = (const float*)d_in[6];
    const float* alpha  = (const float*)d_in[7];
    float* out = (float*)d_out;

    __nv_bfloat16 *wdT, *wuT;
    cudaGetSymbolAddress((void**)&wdT, g_WdT);
    cudaGetSymbolAddress((void**)&wuT, g_WuT);

    cudaFuncSetAttribute(gemm1_kernel, cudaFuncAttributeMaxDynamicSharedMemorySize, DYN_BYTES);
    cudaFuncSetAttribute(gemm2_kernel, cudaFuncAttributeMaxDynamicSharedMemorySize, DYN_BYTES);

    dim3 tb(32, 8);
    transpose_bf16_kernel<<<dim3(DBOT / 32, DIM / 32), tb>>>(Wd, DIM, DBOT, wdT);
    transpose_bf16_kernel<<<dim3(DIM / 32, DBOT / 32), tb>>>(Wu, DBOT, DIM, wuT);
    ln_norm_kernel<<<T_ROWS, 256>>>(hidden, gamma, beta);
    gemm1_kernel<<<dim3(DBOT / BN, T_ROWS / BM), THREADS, DYN_BYTES>>>(bd);
    gemm2_kernel<<<dim3(DIM / BN, T_ROWS / BM), THREADS, DYN_BYTES>>>(hidden, bu, alpha, out);
}

// round 16
// speedup vs baseline: 1.3231x; 1.3231x over previous
#include <cuda_runtime.h>
#include <cuda_bf16.h>
#include <cstdint>

// Problem dims (fixed): B=4, S=4096, D=2048, Db=512
#define T_ROWS 16384
#define DIM    2048
#define DBOT   512
#define LN_EPS 1e-5f

// FP8 GEMM tiling (byte units; fp8 = 1 B/elt)
#define BM 64
#define BN 64
#define KTB 128                        // K bytes per tile (128 fp8 elements, 4 k-steps)
#define BKB 144                        // padded row stride bytes (16B-aligned; banks 4r mod 32 distinct)
#define STAGES 3
#define STAGE_BYTES ((BM + BN) * BKB)  // 18432
#define DYN_BYTES (STAGES * STAGE_BYTES)  // 55296
#define THREADS 128

#define WD_SCALE 64.f
#define WU_SCALE 32.f

// ---------------------------------------------------------------------------
// Device scratch (allocation forbidden -> __device__ globals)
// ---------------------------------------------------------------------------
__device__ unsigned char g_hn[(size_t)T_ROWS * DIM];    // 32 MB fp8 normalized hidden
__device__ unsigned char g_z[(size_t)T_ROWS * DBOT];    // 8 MB fp8 bottleneck activations
__device__ unsigned char g_WdT[(size_t)DBOT * DIM];     // W_down^T * 64, fp8  [n][k]
__device__ unsigned char g_WuT[(size_t)DIM * DBOT];     // W_up^T   * 32, fp8  [n][k]

// ---------------------------------------------------------------------------
// PTX helpers
// ---------------------------------------------------------------------------
__device__ __forceinline__ unsigned smem_u32(const void* p) {
    return (unsigned)__cvta_generic_to_shared(p);
}
__device__ __forceinline__ void cpa16(unsigned dst, const void* src) {
    asm volatile("cp.async.cg.shared.global [%0], [%1], 16;\n" :: "r"(dst), "l"(src));
}
__device__ __forceinline__ void cpa_commit() {
    asm volatile("cp.async.commit_group;\n");
}
template <int N>
__device__ __forceinline__ void cpa_wait() {
    asm volatile("cp.async.wait_group %0;\n" :: "n"(N));
}
__device__ __forceinline__ void ldsm_x4(unsigned& r0, unsigned& r1, unsigned& r2, unsigned& r3,
                                        unsigned addr) {
    asm volatile("ldmatrix.sync.aligned.m8n8.x4.shared.b16 {%0,%1,%2,%3}, [%4];\n"
                 : "=r"(r0), "=r"(r1), "=r"(r2), "=r"(r3) : "r"(addr));
}
// FP8 e4m3 MMA: 16x8x32, fp32 accumulate
__device__ __forceinline__ void mma_f8(float c[4], const unsigned a[4], const unsigned b[2]) {
    asm volatile(
        "mma.sync.aligned.m16n8k32.row.col.f32.e4m3.e4m3.f32 "
        "{%0,%1,%2,%3}, {%4,%5,%6,%7}, {%8,%9}, {%0,%1,%2,%3};\n"
        : "+f"(c[0]), "+f"(c[1]), "+f"(c[2]), "+f"(c[3])
        : "r"(a[0]), "r"(a[1]), "r"(a[2]), "r"(a[3]), "r"(b[0]), "r"(b[1]));
}
__device__ __forceinline__ unsigned short pack_fp8x2(float lo, float hi) {
    unsigned short r;
    asm("cvt.rn.satfinite.e4m3x2.f32 %0, %1, %2;" : "=h"(r) : "f"(hi), "f"(lo));
    return r;
}
__device__ __forceinline__ unsigned pack_fp8x4(float a, float b, float c, float d) {
    unsigned short lo = pack_fp8x2(a, b);
    unsigned short hi = pack_fp8x2(c, d);
    return (unsigned)lo | ((unsigned)hi << 16);
}
__device__ __forceinline__ unsigned char f2fp8(float v) {
    return (unsigned char)pack_fp8x2(v, 0.f);
}
__device__ __forceinline__ float silu(float v) {
    return v * (1.f / (1.f + __expf(-v)));
}

// ---------------------------------------------------------------------------
// Fused LayerNorm -> fp8 h_norm
// ---------------------------------------------------------------------------
__global__ __launch_bounds__(256) void ln_norm_kernel(
    const float* __restrict__ hidden,
    const float* __restrict__ gamma,
    const float* __restrict__ beta)
{
    const int row = blockIdx.x;
    const int t = threadIdx.x;
    const int warp = t >> 5, lane = t & 31;

    const float4* hp = reinterpret_cast<const float4*>(hidden + (size_t)row * DIM);
    float4 v0 = hp[t], v1 = hp[t + 256];

    float s  = v0.x + v0.y + v0.z + v0.w + v1.x + v1.y + v1.z + v1.w;
    float ss = v0.x * v0.x + v0.y * v0.y + v0.z * v0.z + v0.w * v0.w
             + v1.x * v1.x + v1.y * v1.y + v1.z * v1.z + v1.w * v1.w;
#pragma unroll
    for (int o = 16; o > 0; o >>= 1) {
        s  += __shfl_xor_sync(0xffffffffu, s, o);
        ss += __shfl_xor_sync(0xffffffffu, ss, o);
    }
    __shared__ float rs[8], rss[8], stats[2];
    if (lane == 0) { rs[warp] = s; rss[warp] = ss; }
    __syncthreads();
    if (warp == 0) {
        float s2  = (lane < 8) ? rs[lane]  : 0.f;
        float ss2 = (lane < 8) ? rss[lane] : 0.f;
#pragma unroll
        for (int o = 4; o > 0; o >>= 1) {
            s2  += __shfl_xor_sync(0xffffffffu, s2, o);
            ss2 += __shfl_xor_sync(0xffffffffu, ss2, o);
        }
        if (lane == 0) {
            float mu  = s2 * (1.f / DIM);
            float var = ss2 * (1.f / DIM) - mu * mu;
            stats[0] = mu;
            stats[1] = rsqrtf(var + LN_EPS);
        }
    }
    __syncthreads();
    const float mu = stats[0], rstd = stats[1];

    const float4* gp = reinterpret_cast<const float4*>(gamma);
    const float4* bp = reinterpret_cast<const float4*>(beta);
    float4 g0 = gp[t], g1 = gp[t + 256];
    float4 b0 = bp[t], b1 = bp[t + 256];

    unsigned* dst = reinterpret_cast<unsigned*>(g_hn + (size_t)row * DIM);
    dst[t] = pack_fp8x4((v0.x - mu) * rstd * g0.x + b0.x,
                        (v0.y - mu) * rstd * g0.y + b0.y,
                        (v0.z - mu) * rstd * g0.z + b0.z,
                        (v0.w - mu) * rstd * g0.w + b0.w);
    dst[t + 256] = pack_fp8x4((v1.x - mu) * rstd * g1.x + b1.x,
                              (v1.y - mu) * rstd * g1.y + b1.y,
                              (v1.z - mu) * rstd * g1.z + b1.z,
                              (v1.w - mu) * rstd * g1.w + b1.w);
}

// ---------------------------------------------------------------------------
// fp32 [R][C] -> fp8 transposed [C][R], scaled
// ---------------------------------------------------------------------------
__global__ void transpose_fp8_kernel(const float* __restrict__ src, int R, int C,
                                     unsigned char* __restrict__ dst, float scale)
{
    __shared__ float tile[32][33];
    int x  = blockIdx.x * 32 + threadIdx.x;
    int y0 = blockIdx.y * 32;
#pragma unroll
    for (int j = 0; j < 32; j += 8)
        tile[threadIdx.y + j][threadIdx.x] = src[(size_t)(y0 + threadIdx.y + j) * C + x];
    __syncthreads();
    int xr  = blockIdx.y * 32 + threadIdx.x;
    int yc0 = blockIdx.x * 32;
#pragma unroll
    for (int j = 0; j < 32; j += 8)
        dst[(size_t)(yc0 + threadIdx.y + j) * R + xr] =
            f2fp8(tile[threadIdx.x][threadIdx.y + j] * scale);
}

// ---------------------------------------------------------------------------
// FP8 GEMM mainloop: 64x64 CTA tile, 4 warps (warp tile 32x32).
// KTB=128: 128-byte K-tiles (4 m16n8k32 k-steps per tile) -> HALVED iteration
// count vs KTB=64; per-iteration overhead (barrier/wait/LDSM serialization)
// is the empirically binding cost, so fewer, fatter tiles.
// 3-stage cp.async pipeline, prefetch distance 2, wait_group<1>, one
// __syncthreads per K-tile. Slot for tile it+2 was computed 2 syncs ago -> no
// WAR hazard.
// ---------------------------------------------------------------------------
__device__ __forceinline__ void gemm_mainloop(
    const unsigned char* __restrict__ Ag, int ldaB,
    const unsigned char* __restrict__ Bg, int ldbB,
    int KBytes, int rowBase, int n0,
    unsigned sbase,
    float c[2][4][4])
{
    const int tid  = threadIdx.x;
    const int warp = tid >> 5, lane = tid & 31;
    const int wm = warp >> 1, wn = warp & 1;     // 2x2 warp grid, 32x32 tiles

    const int aRow     = ((lane >> 3) & 1) * 8 + (lane & 7);
    const int aColOffB = (lane >> 4) * 16;
    const int bRow     = (lane >> 4) * 8 + (lane & 7);
    const int bColOffB = ((lane >> 3) & 1) * 16;

    // warp-invariant fragment base addresses (slot 0, k-offset 0)
    unsigned aBase[2], bBase[2];
#pragma unroll
    for (int mi = 0; mi < 2; ++mi)
        aBase[mi] = sbase + (unsigned)((wm * 32 + mi * 16 + aRow) * BKB + aColOffB);
#pragma unroll
    for (int p = 0; p < 2; ++p)
        bBase[p] = sbase + (unsigned)(BM * BKB + (wn * 32 + p * 16 + bRow) * BKB + bColOffB);

    // per-thread load state: 4 A rows + 4 B rows, 16B each
    // (64 rows x 128B per operand; 128 threads -> 8 chunks/thread)
    const int r0i = tid >> 3;            // 0..15
    const int ci  = (tid & 7) * 16;      // 0..112
    const unsigned dA = sbase + (unsigned)(r0i * BKB + ci);
    const unsigned dB = sbase + (unsigned)(BM * BKB + r0i * BKB + ci);
    const unsigned char* pA = Ag + (size_t)(rowBase + r0i) * ldaB + ci;
    const unsigned char* pB = Bg + (size_t)(n0 + r0i) * ldbB + ci;

    const int niter = KBytes / KTB;   // 16 (gemm1) / 4 (gemm2)

    // prologue: tiles 0,1 -> slots 0,1
#pragma unroll
    for (int s = 0; s < 2; ++s) {
        const unsigned off = (unsigned)(s * STAGE_BYTES);
#pragma unroll
        for (int p = 0; p < 4; ++p) {
            cpa16(dA + off + (unsigned)(p * 16 * BKB), pA + (size_t)(p * 16) * ldaB);
            cpa16(dB + off + (unsigned)(p * 16 * BKB), pB + (size_t)(p * 16) * ldbB);
        }
        cpa_commit();
        pA += KTB; pB += KTB;
    }

    int slot = 0, nslot = 2;
    for (int it = 0; it < niter; ++it) {
        cpa_wait<1>();          // tile 'it' resident (tile it+1 may be in flight)
        __syncthreads();        // slot 'nslot' computed 2 iterations ago -> free

        if (it + 2 < niter) {
            const unsigned off = (unsigned)(nslot * STAGE_BYTES);
#pragma unroll
            for (int p = 0; p < 4; ++p) {
                cpa16(dA + off + (unsigned)(p * 16 * BKB), pA + (size_t)(p * 16) * ldaB);
                cpa16(dB + off + (unsigned)(p * 16 * BKB), pB + (size_t)(p * 16) * ldbB);
            }
            pA += KTB; pB += KTB;
        }
        cpa_commit();

        const unsigned soff = (unsigned)(slot * STAGE_BYTES);
#pragma unroll
        for (int kkB = 0; kkB < KTB; kkB += 32) {    // one m16n8k32 step = 32 B of K
            unsigned a[2][4], b[4][2];
#pragma unroll
            for (int mi = 0; mi < 2; ++mi)
                ldsm_x4(a[mi][0], a[mi][1], a[mi][2], a[mi][3],
                        aBase[mi] + soff + (unsigned)kkB);
#pragma unroll
            for (int p = 0; p < 2; ++p)
                ldsm_x4(b[2 * p][0], b[2 * p][1], b[2 * p + 1][0], b[2 * p + 1][1],
                        bBase[p] + soff + (unsigned)kkB);
#pragma unroll
            for (int mi = 0; mi < 2; ++mi)
#pragma unroll
                for (int ni = 0; ni < 4; ++ni)
                    mma_f8(c[mi][ni], a[mi], b[ni]);
        }

        slot  = (slot == STAGES - 1) ? 0 : slot + 1;
        nslot = (nslot == STAGES - 1) ? 0 : nslot + 1;
    }
}

// ---------------------------------------------------------------------------
// GEMM1: z = SiLU( h_norm @ (W_down*64) / 64 + b_down )  -> fp8 g_z
// ---------------------------------------------------------------------------
__global__ __launch_bounds__(THREADS, 4) void gemm1_kernel(const float* __restrict__ bd)
{
    extern __shared__ __align__(16) unsigned char smem[];

    const int tid  = threadIdx.x;
    const int warp = tid >> 5, lane = tid & 31;
    const int wm = warp >> 1, wn = warp & 1;
    const int group = lane >> 2, tg = lane & 3;
    const int rowBase = blockIdx.y * BM;
    const int n0      = blockIdx.x * BN;

    float c[2][4][4];
#pragma unroll
    for (int i = 0; i < 2; i++)
#pragma unroll
        for (int j = 0; j < 4; j++)
#pragma unroll
            for (int k = 0; k < 4; k++) c[i][j][k] = 0.f;

    gemm_mainloop(g_hn, DIM, g_WdT, DIM, DIM, rowBase, n0, smem_u32(smem), c);

    const float inv = 1.f / WD_SCALE;
#pragma unroll
    for (int mi = 0; mi < 2; ++mi) {
        int r0 = rowBase + wm * 32 + mi * 16 + group;
#pragma unroll
        for (int ni = 0; ni < 4; ++ni) {
            int cc = n0 + wn * 32 + ni * 8 + tg * 2;
            float bd0 = bd[cc], bd1 = bd[cc + 1];
            *reinterpret_cast<unsigned short*>(&g_z[(size_t)r0 * DBOT + cc]) =
                pack_fp8x2(silu(c[mi][ni][0] * inv + bd0), silu(c[mi][ni][1] * inv + bd1));
            *reinterpret_cast<unsigned short*>(&g_z[(size_t)(r0 + 8) * DBOT + cc]) =
                pack_fp8x2(silu(c[mi][ni][2] * inv + bd0), silu(c[mi][ni][3] * inv + bd1));
        }
    }
}

// ---------------------------------------------------------------------------
// GEMM2: out = hidden + alpha * ( z @ (W_up*32)/32 + b_up - hidden )
// ---------------------------------------------------------------------------
__global__ __launch_bounds__(THREADS, 4) void gemm2_kernel(
    const float* __restrict__ hidden,
    const float* __restrict__ bu,
    const float* __restrict__ alpha_p,
    float* __restrict__ out)
{
    extern __shared__ __align__(16) unsigned char smem[];

    const int tid  = threadIdx.x;
    const int warp = tid >> 5, lane = tid & 31;
    const int wm = warp >> 1, wn = warp & 1;
    const int group = lane >> 2, tg = lane & 3;
    const int rowBase = blockIdx.y * BM;
    const int n0      = blockIdx.x * BN;

    float c[2][4][4];
#pragma unroll
    for (int i = 0; i < 2; i++)
#pragma unroll
        for (int j = 0; j < 4; j++)
#pragma unroll
            for (int k = 0; k < 4; k++) c[i][j][k] = 0.f;

    gemm_mainloop(g_z, DBOT, g_WuT, DBOT, DBOT, rowBase, n0, smem_u32(smem), c);

    const float al = alpha_p[0];
    const float inv = 1.f / WU_SCALE;
#pragma unroll
    for (int mi = 0; mi < 2; ++mi) {
        int r0 = rowBase + wm * 32 + mi * 16 + group;
        int r1 = r0 + 8;
#pragma unroll
        for (int ni = 0; ni < 4; ++ni) {
            int cc = n0 + wn * 32 + ni * 8 + tg * 2;
            float bu0 = bu[cc], bu1 = bu[cc + 1];

            float2 h0 = *reinterpret_cast<const float2*>(hidden + (size_t)r0 * DIM + cc);
            float2 h1 = *reinterpret_cast<const float2*>(hidden + (size_t)r1 * DIM + cc);

            float2 o0, o1;
            o0.x = h0.x + al * (c[mi][ni][0] * inv + bu0 - h0.x);
            o0.y = h0.y + al * (c[mi][ni][1] * inv + bu1 - h0.y);
            o1.x = h1.x + al * (c[mi][ni][2] * inv + bu0 - h1.x);
            o1.y = h1.y + al * (c[mi][ni][3] * inv + bu1 - h1.y);

            *reinterpret_cast<float2*>(out + (size_t)r0 * DIM + cc) = o0;
            *reinterpret_cast<float2*>(out + (size_t)r1 * DIM + cc) = o1;
        }
    }
}

// ---------------------------------------------------------------------------
// Launch
// ---------------------------------------------------------------------------
extern "C" void kernel_launch(void* const* d_in, const int* in_sizes, int n_in,
                              void* d_out, int out_size) {
    const float* hidden = (const float*)d_in[0];
    const float* gamma  = (const float*)d_in[1];
    const float* beta   = (const float*)d_in[2];
    const float* Wd     = (const float*)d_in[3];
    const float* bd     = (const float*)d_in[4];
    const float* Wu     = (const float*)d_in[5];
    const float* bu     = (const float*)d_in[6];
    const float* alpha  = (const float*)d_in[7];
    float* out = (float*)d_out;

    unsigned char *wdT, *wuT;
    cudaGetSymbolAddress((void**)&wdT, g_WdT);
    cudaGetSymbolAddress((void**)&wuT, g_WuT);

    cudaFuncSetAttribute(gemm1_kernel, cudaFuncAttributeMaxDynamicSharedMemorySize, DYN_BYTES);
    cudaFuncSetAttribute(gemm2_kernel, cudaFuncAttributeMaxDynamicSharedMemorySize, DYN_BYTES);

    dim3 tb(32, 8);
    transpose_fp8_kernel<<<dim3(DBOT / 32, DIM / 32), tb>>>(Wd, DIM, DBOT, wdT, WD_SCALE);
    transpose_fp8_kernel<<<dim3(DIM / 32, DBOT / 32), tb>>>(Wu, DBOT, DIM, wuT, WU_SCALE);
    ln_norm_kernel<<<T_ROWS, 256>>>(hidden, gamma, beta);
    gemm1_kernel<<<dim3(DBOT / BN, T_ROWS / BM), THREADS, DYN_BYTES>>>(bd);
    gemm2_kernel<<<dim3(DIM / BN, T_ROWS / BM), THREADS, DYN_BYTES>>>(hidden, bu, alpha, out);
}

// round 17
// speedup vs baseline: 1.4840x; 1.1216x over previous
#include <cuda_runtime.h>
#include <cuda_bf16.h>
#include <cstdint>

// Problem dims (fixed): B=4, S=4096, D=2048, Db=512
#define T_ROWS 16384
#define DIM    2048
#define DBOT   512
#define LN_EPS 1e-5f

// FP8-storage GEMM tiling (byte units; fp8 = 1 B/elt). Math: manual
// e4m3->f16 conversion + f16 HMMA (exact, no per-MMA emulation tax).
#define BM 64
#define BN 64
#define KTB 128                        // K bytes per tile (128 fp8 elements, 4 k-steps)
#define BKB 144                        // padded row stride bytes (16B-aligned cp.async)
#define STAGES 3
#define STAGE_BYTES ((BM + BN) * BKB)  // 18432
#define DYN_BYTES (STAGES * STAGE_BYTES)  // 55296
#define THREADS 128

#define WD_SCALE 64.f
#define WU_SCALE 32.f

// ---------------------------------------------------------------------------
// Device scratch (allocation forbidden -> __device__ globals)
// ---------------------------------------------------------------------------
__device__ unsigned char g_hn[(size_t)T_ROWS * DIM];    // 32 MB fp8 normalized hidden
__device__ unsigned char g_z[(size_t)T_ROWS * DBOT];    // 8 MB fp8 bottleneck activations
__device__ unsigned char g_WdT[(size_t)DBOT * DIM];     // W_down^T * 64, fp8  [n][k]
__device__ unsigned char g_WuT[(size_t)DIM * DBOT];     // W_up^T   * 32, fp8  [n][k]

// ---------------------------------------------------------------------------
// PTX helpers
// ---------------------------------------------------------------------------
__device__ __forceinline__ unsigned smem_u32(const void* p) {
    return (unsigned)__cvta_generic_to_shared(p);
}
__device__ __forceinline__ void cpa16(unsigned dst, const void* src) {
    asm volatile("cp.async.cg.shared.global [%0], [%1], 16;\n" :: "r"(dst), "l"(src));
}
__device__ __forceinline__ void cpa_commit() {
    asm volatile("cp.async.commit_group;\n");
}
template <int N>
__device__ __forceinline__ void cpa_wait() {
    asm volatile("cp.async.wait_group %0;\n" :: "n"(N));
}
__device__ __forceinline__ void ldsm_x4(unsigned& r0, unsigned& r1, unsigned& r2, unsigned& r3,
                                        unsigned addr) {
    asm volatile("ldmatrix.sync.aligned.m8n8.x4.shared.b16 {%0,%1,%2,%3}, [%4];\n"
                 : "=r"(r0), "=r"(r1), "=r"(r2), "=r"(r3) : "r"(addr));
}
// f16 HMMA: 16x8x16, fp32 accumulate (native rate, no conversion tax)
__device__ __forceinline__ void mma_f16(float c[4], const unsigned a[4], const unsigned b[2]) {
    asm volatile(
        "mma.sync.aligned.m16n8k16.row.col.f32.f16.f16.f32 "
        "{%0,%1,%2,%3}, {%4,%5,%6,%7}, {%8,%9}, {%0,%1,%2,%3};\n"
        : "+f"(c[0]), "+f"(c[1]), "+f"(c[2]), "+f"(c[3])
        : "r"(a[0]), "r"(a[1]), "r"(a[2]), "r"(a[3]), "r"(b[0]), "r"(b[1]));
}
// Convert one fp8x4 reg (4 consecutive-K e4m3) -> two f16x2 regs:
// lo = f16 pair (k+0, k+1), hi = f16 pair (k+2, k+3). e4m3 -> f16 is EXACT.
__device__ __forceinline__ void cvt_fp8x4(unsigned x, unsigned& lo, unsigned& hi) {
    asm("{\n\t"
        ".reg .b16 l, h;\n\t"
        "mov.b32 {l, h}, %2;\n\t"
        "cvt.rn.f16x2.e4m3x2 %0, l;\n\t"
        "cvt.rn.f16x2.e4m3x2 %1, h;\n\t"
        "}"
        : "=r"(lo), "=r"(hi) : "r"(x));
}
__device__ __forceinline__ unsigned short pack_fp8x2(float lo, float hi) {
    unsigned short r;
    asm("cvt.rn.satfinite.e4m3x2.f32 %0, %1, %2;" : "=h"(r) : "f"(hi), "f"(lo));
    return r;
}
__device__ __forceinline__ unsigned pack_fp8x4(float a, float b, float c, float d) {
    unsigned short lo = pack_fp8x2(a, b);
    unsigned short hi = pack_fp8x2(c, d);
    return (unsigned)lo | ((unsigned)hi << 16);
}
__device__ __forceinline__ unsigned char f2fp8(float v) {
    return (unsigned char)pack_fp8x2(v, 0.f);
}
__device__ __forceinline__ float silu(float v) {
    return v * (1.f / (1.f + __expf(-v)));
}

// ---------------------------------------------------------------------------
// Fused LayerNorm -> fp8 h_norm
// ---------------------------------------------------------------------------
__global__ __launch_bounds__(256) void ln_norm_kernel(
    const float* __restrict__ hidden,
    const float* __restrict__ gamma,
    const float* __restrict__ beta)
{
    const int row = blockIdx.x;
    const int t = threadIdx.x;
    const int warp = t >> 5, lane = t & 31;

    const float4* hp = reinterpret_cast<const float4*>(hidden + (size_t)row * DIM);
    float4 v0 = hp[t], v1 = hp[t + 256];

    float s  = v0.x + v0.y + v0.z + v0.w + v1.x + v1.y + v1.z + v1.w;
    float ss = v0.x * v0.x + v0.y * v0.y + v0.z * v0.z + v0.w * v0.w
             + v1.x * v1.x + v1.y * v1.y + v1.z * v1.z + v1.w * v1.w;
#pragma unroll
    for (int o = 16; o > 0; o >>= 1) {
        s  += __shfl_xor_sync(0xffffffffu, s, o);
        ss += __shfl_xor_sync(0xffffffffu, ss, o);
    }
    __shared__ float rs[8], rss[8], stats[2];
    if (lane == 0) { rs[warp] = s; rss[warp] = ss; }
    __syncthreads();
    if (warp == 0) {
        float s2  = (lane < 8) ? rs[lane]  : 0.f;
        float ss2 = (lane < 8) ? rss[lane] : 0.f;
#pragma unroll
        for (int o = 4; o > 0; o >>= 1) {
            s2  += __shfl_xor_sync(0xffffffffu, s2, o);
            ss2 += __shfl_xor_sync(0xffffffffu, ss2, o);
        }
        if (lane == 0) {
            float mu  = s2 * (1.f / DIM);
            float var = ss2 * (1.f / DIM) - mu * mu;
            stats[0] = mu;
            stats[1] = rsqrtf(var + LN_EPS);
        }
    }
    __syncthreads();
    const float mu = stats[0], rstd = stats[1];

    const float4* gp = reinterpret_cast<const float4*>(gamma);
    const float4* bp = reinterpret_cast<const float4*>(beta);
    float4 g0 = gp[t], g1 = gp[t + 256];
    float4 b0 = bp[t], b1 = bp[t + 256];

    unsigned* dst = reinterpret_cast<unsigned*>(g_hn + (size_t)row * DIM);
    dst[t] = pack_fp8x4((v0.x - mu) * rstd * g0.x + b0.x,
                        (v0.y - mu) * rstd * g0.y + b0.y,
                        (v0.z - mu) * rstd * g0.z + b0.z,
                        (v0.w - mu) * rstd * g0.w + b0.w);
    dst[t + 256] = pack_fp8x4((v1.x - mu) * rstd * g1.x + b1.x,
                              (v1.y - mu) * rstd * g1.y + b1.y,
                              (v1.z - mu) * rstd * g1.z + b1.z,
                              (v1.w - mu) * rstd * g1.w + b1.w);
}

// ---------------------------------------------------------------------------
// fp32 [R][C] -> fp8 transposed [C][R], scaled
// ---------------------------------------------------------------------------
__global__ void transpose_fp8_kernel(const float* __restrict__ src, int R, int C,
                                     unsigned char* __restrict__ dst, float scale)
{
    __shared__ float tile[32][33];
    int x  = blockIdx.x * 32 + threadIdx.x;
    int y0 = blockIdx.y * 32;
#pragma unroll
    for (int j = 0; j < 32; j += 8)
        tile[threadIdx.y + j][threadIdx.x] = src[(size_t)(y0 + threadIdx.y + j) * C + x];
    __syncthreads();
    int xr  = blockIdx.y * 32 + threadIdx.x;
    int yc0 = blockIdx.x * 32;
#pragma unroll
    for (int j = 0; j < 32; j += 8)
        dst[(size_t)(yc0 + threadIdx.y + j) * R + xr] =
            f2fp8(tile[threadIdx.x][threadIdx.y + j] * scale);
}

// ---------------------------------------------------------------------------
// GEMM mainloop: 64x64 CTA tile, 4 warps (warp tile 32x32), fp8 storage.
// Per 32B k-step: ldsm fp8 fragments (verified QMMA layout), convert each
// fragment ONCE to f16 (A reused by 4 MMAs, B by 2), then native f16 HMMA.
// The K-permutation (k=4tg+j) is applied identically to A and B slots, so
// the slot-wise products pair identical k values -> exact dot product.
// 3-stage cp.async pipeline, distance 2, wait_group<1>, one sync per K-tile.
// ---------------------------------------------------------------------------
__device__ __forceinline__ void gemm_mainloop(
    const unsigned char* __restrict__ Ag, int ldaB,
    const unsigned char* __restrict__ Bg, int ldbB,
    int KBytes, int rowBase, int n0,
    unsigned sbase,
    float c[2][4][4])
{
    const int tid  = threadIdx.x;
    const int warp = tid >> 5, lane = tid & 31;
    const int wm = warp >> 1, wn = warp & 1;     // 2x2 warp grid, 32x32 tiles

    const int aRow     = ((lane >> 3) & 1) * 8 + (lane & 7);
    const int aColOffB = (lane >> 4) * 16;
    const int bRow     = (lane >> 4) * 8 + (lane & 7);
    const int bColOffB = ((lane >> 3) & 1) * 16;

    // warp-invariant fragment base addresses (slot 0, k-offset 0)
    unsigned aBase[2], bBase[2];
#pragma unroll
    for (int mi = 0; mi < 2; ++mi)
        aBase[mi] = sbase + (unsigned)((wm * 32 + mi * 16 + aRow) * BKB + aColOffB);
#pragma unroll
    for (int p = 0; p < 2; ++p)
        bBase[p] = sbase + (unsigned)(BM * BKB + (wn * 32 + p * 16 + bRow) * BKB + bColOffB);

    // per-thread load state: 8 x 16B chunks (64 rows x 128B per operand)
    const int r0i = tid >> 3;            // 0..15
    const int ci  = (tid & 7) * 16;      // 0..112
    const unsigned dA = sbase + (unsigned)(r0i * BKB + ci);
    const unsigned dB = sbase + (unsigned)(BM * BKB + r0i * BKB + ci);
    const unsigned char* pA = Ag + (size_t)(rowBase + r0i) * ldaB + ci;
    const unsigned char* pB = Bg + (size_t)(n0 + r0i) * ldbB + ci;

    const int niter = KBytes / KTB;   // 16 (gemm1) / 4 (gemm2)

    // prologue: tiles 0,1 -> slots 0,1
#pragma unroll
    for (int s = 0; s < 2; ++s) {
        const unsigned off = (unsigned)(s * STAGE_BYTES);
#pragma unroll
        for (int p = 0; p < 4; ++p) {
            cpa16(dA + off + (unsigned)(p * 16 * BKB), pA + (size_t)(p * 16) * ldaB);
            cpa16(dB + off + (unsigned)(p * 16 * BKB), pB + (size_t)(p * 16) * ldbB);
        }
        cpa_commit();
        pA += KTB; pB += KTB;
    }

    int slot = 0, nslot = 2;
    for (int it = 0; it < niter; ++it) {
        cpa_wait<1>();          // tile 'it' resident (tile it+1 may be in flight)
        __syncthreads();        // slot 'nslot' computed 2 iterations ago -> free

        if (it + 2 < niter) {
            const unsigned off = (unsigned)(nslot * STAGE_BYTES);
#pragma unroll
            for (int p = 0; p < 4; ++p) {
                cpa16(dA + off + (unsigned)(p * 16 * BKB), pA + (size_t)(p * 16) * ldaB);
                cpa16(dB + off + (unsigned)(p * 16 * BKB), pB + (size_t)(p * 16) * ldbB);
            }
            pA += KTB; pB += KTB;
        }
        cpa_commit();

        const unsigned soff = (unsigned)(slot * STAGE_BYTES);
#pragma unroll
        for (int kkB = 0; kkB < KTB; kkB += 32) {    // 32 B of K per step
            unsigned a8[2][4], b8[4][2];
#pragma unroll
            for (int mi = 0; mi < 2; ++mi)
                ldsm_x4(a8[mi][0], a8[mi][1], a8[mi][2], a8[mi][3],
                        aBase[mi] + soff + (unsigned)kkB);
#pragma unroll
            for (int p = 0; p < 2; ++p)
                ldsm_x4(b8[2 * p][0], b8[2 * p][1], b8[2 * p + 1][0], b8[2 * p + 1][1],
                        bBase[p] + soff + (unsigned)kkB);

            // ---- convert once per fragment (A reused 4x, B reused 2x) ----
            // f16 a-slots: {lo(a0), lo(a1), hi(a0), hi(a1)} covers fp8 k[0:16)
            //              {lo(a2), lo(a3), hi(a2), hi(a3)} covers fp8 k[16:32)
            unsigned ah[2][2][4];
#pragma unroll
            for (int mi = 0; mi < 2; ++mi) {
                cvt_fp8x4(a8[mi][0], ah[mi][0][0], ah[mi][0][2]);
                cvt_fp8x4(a8[mi][1], ah[mi][0][1], ah[mi][0][3]);
                cvt_fp8x4(a8[mi][2], ah[mi][1][0], ah[mi][1][2]);
                cvt_fp8x4(a8[mi][3], ah[mi][1][1], ah[mi][1][3]);
            }
            unsigned bh[4][2][2];
#pragma unroll
            for (int ni = 0; ni < 4; ++ni) {
                cvt_fp8x4(b8[ni][0], bh[ni][0][0], bh[ni][0][1]);
                cvt_fp8x4(b8[ni][1], bh[ni][1][0], bh[ni][1][1]);
            }

#pragma unroll
            for (int mi = 0; mi < 2; ++mi)
#pragma unroll
                for (int ni = 0; ni < 4; ++ni) {
                    mma_f16(c[mi][ni], ah[mi][0], bh[ni][0]);
                    mma_f16(c[mi][ni], ah[mi][1], bh[ni][1]);
                }
        }

        slot  = (slot == STAGES - 1) ? 0 : slot + 1;
        nslot = (nslot == STAGES - 1) ? 0 : nslot + 1;
    }
}

// ---------------------------------------------------------------------------
// GEMM1: z = SiLU( h_norm @ (W_down*64) / 64 + b_down )  -> fp8 g_z
// ---------------------------------------------------------------------------
__global__ __launch_bounds__(THREADS, 4) void gemm1_kernel(const float* __restrict__ bd)
{
    extern __shared__ __align__(16) unsigned char smem[];

    const int tid  = threadIdx.x;
    const int warp = tid >> 5, lane = tid & 31;
    const int wm = warp >> 1, wn = warp & 1;
    const int group = lane >> 2, tg = lane & 3;
    const int rowBase = blockIdx.y * BM;
    const int n0      = blockIdx.x * BN;

    float c[2][4][4];
#pragma unroll
    for (int i = 0; i < 2; i++)
#pragma unroll
        for (int j = 0; j < 4; j++)
#pragma unroll
            for (int k = 0; k < 4; k++) c[i][j][k] = 0.f;

    gemm_mainloop(g_hn, DIM, g_WdT, DIM, DIM, rowBase, n0, smem_u32(smem), c);

    const float inv = 1.f / WD_SCALE;
#pragma unroll
    for (int mi = 0; mi < 2; ++mi) {
        int r0 = rowBase + wm * 32 + mi * 16 + group;
#pragma unroll
        for (int ni = 0; ni < 4; ++ni) {
            int cc = n0 + wn * 32 + ni * 8 + tg * 2;
            float bd0 = bd[cc], bd1 = bd[cc + 1];
            *reinterpret_cast<unsigned short*>(&g_z[(size_t)r0 * DBOT + cc]) =
                pack_fp8x2(silu(c[mi][ni][0] * inv + bd0), silu(c[mi][ni][1] * inv + bd1));
            *reinterpret_cast<unsigned short*>(&g_z[(size_t)(r0 + 8) * DBOT + cc]) =
                pack_fp8x2(silu(c[mi][ni][2] * inv + bd0), silu(c[mi][ni][3] * inv + bd1));
        }
    }
}

// ---------------------------------------------------------------------------
// GEMM2: out = hidden + alpha * ( z @ (W_up*32)/32 + b_up - hidden )
// ---------------------------------------------------------------------------
__global__ __launch_bounds__(THREADS, 4) void gemm2_kernel(
    const float* __restrict__ hidden,
    const float* __restrict__ bu,
    const float* __restrict__ alpha_p,
    float* __restrict__ out)
{
    extern __shared__ __align__(16) unsigned char smem[];

    const int tid  = threadIdx.x;
    const int warp = tid >> 5, lane = tid & 31;
    const int wm = warp >> 1, wn = warp & 1;
    const int group = lane >> 2, tg = lane & 3;
    const int rowBase = blockIdx.y * BM;
    const int n0      = blockIdx.x * BN;

    float c[2][4][4];
#pragma unroll
    for (int i = 0; i < 2; i++)
#pragma unroll
        for (int j = 0; j < 4; j++)
#pragma unroll
            for (int k = 0; k < 4; k++) c[i][j][k] = 0.f;

    gemm_mainloop(g_z, DBOT, g_WuT, DBOT, DBOT, rowBase, n0, smem_u32(smem), c);

    const float al = alpha_p[0];
    const float inv = 1.f / WU_SCALE;
#pragma unroll
    for (int mi = 0; mi < 2; ++mi) {
        int r0 = rowBase + wm * 32 + mi * 16 + group;
        int r1 = r0 + 8;
#pragma unroll
        for (int ni = 0; ni < 4; ++ni) {
            int cc = n0 + wn * 32 + ni * 8 + tg * 2;
            float bu0 = bu[cc], bu1 = bu[cc + 1];

            float2 h0 = *reinterpret_cast<const float2*>(hidden + (size_t)r0 * DIM + cc);
            float2 h1 = *reinterpret_cast<const float2*>(hidden + (size_t)r1 * DIM + cc);

            float2 o0, o1;
            o0.x = h0.x + al * (c[mi][ni][0] * inv + bu0 - h0.x);
            o0.y = h0.y + al * (c[mi][ni][1] * inv + bu1 - h0.y);
            o1.x = h1.x + al * (c[mi][ni][2] * inv + bu0 - h1.x);
            o1.y = h1.y + al * (c[mi][ni][3] * inv + bu1 - h1.y);

            *reinterpret_cast<float2*>(out + (size_t)r0 * DIM + cc) = o0;
            *reinterpret_cast<float2*>(out + (size_t)r1 * DIM + cc) = o1;
        }
    }
}

// ---------------------------------------------------------------------------
// Launch
// ---------------------------------------------------------------------------
extern "C" void kernel_launch(void* const* d_in, const int* in_sizes, int n_in,
                              void* d_out, int out_size) {
    const float* hidden = (const float*)d_in[0];
    const float* gamma  = (const float*)d_in[1];
    const float* beta   = (const float*)d_in[2];
    const float* Wd     = (const float*)d_in[3];
    const float* bd     = (const float*)d_in[4];
    const float* Wu     = (const float*)d_in[5];
    const float* bu     = (const float*)d_in[6];
    const float* alpha  = (const float*)d_in[7];
    float* out = (float*)d_out;

    unsigned char *wdT, *wuT;
    cudaGetSymbolAddress((void**)&wdT, g_WdT);
    cudaGetSymbolAddress((void**)&wuT, g_WuT);

    cudaFuncSetAttribute(gemm1_kernel, cudaFuncAttributeMaxDynamicSharedMemorySize, DYN_BYTES);
    cudaFuncSetAttribute(gemm2_kernel, cudaFuncAttributeMaxDynamicSharedMemorySize, DYN_BYTES);

    dim3 tb(32, 8);
    transpose_fp8_kernel<<<dim3(DBOT / 32, DIM / 32), tb>>>(Wd, DIM, DBOT, wdT, WD_SCALE);
    transpose_fp8_kernel<<<dim3(DIM / 32, DBOT / 32), tb>>>(Wu, DBOT, DIM, wuT, WU_SCALE);
    ln_norm_kernel<<<T_ROWS, 256>>>(hidden, gamma, beta);
    gemm1_kernel<<<dim3(DBOT / BN, T_ROWS / BM), THREADS, DYN_BYTES>>>(bd);
    gemm2_kernel<<<dim3(DIM / BN, T_ROWS / BM), THREADS, DYN_BYTES>>>(hidden, bu, alpha, out);
}